// round 1
// baseline (speedup 1.0000x reference)
#include <cuda_runtime.h>
#include <math.h>

#define L       4096
#define INDIM   1024
#define DM      512
#define DIN     2048
#define DSTATE  256
#define CONVD   2560
#define DPROJ   4640
#define NH      32
#define HD      64
#define EPSV    1e-5f

// ------------------------- scratch (device globals; no allocs allowed) ----
__device__ __align__(256) float g_h  [L * DM];
__device__ __align__(256) float g_hn [L * DM];
__device__ __align__(256) float g_zx [(size_t)L * DPROJ];
__device__ __align__(256) float g_xbc[(size_t)L * CONVD];
__device__ __align__(256) float g_dt [L * NH];
__device__ __align__(256) float g_y  [(size_t)L * DIN];
__device__ __align__(256) float g_yn [(size_t)L * DIN];
__device__ __align__(256) float g_s1 [L * 128];
__device__ __align__(256) float g_alog[L];
__device__ __align__(256) float g_att [L];
__device__ __align__(256) float g_part[32 * DM];

// ------------------------- helpers ---------------------------------------
__device__ __forceinline__ float blk_sum(float v, float* sbuf) {
    int lane = threadIdx.x & 31, w = threadIdx.x >> 5;
    int nw = blockDim.x >> 5;
#pragma unroll
    for (int o = 16; o; o >>= 1) v += __shfl_xor_sync(0xffffffffu, v, o);
    if (lane == 0) sbuf[w] = v;
    __syncthreads();
    float r = (threadIdx.x < nw) ? sbuf[threadIdx.x] : 0.f;
    if (w == 0) {
#pragma unroll
        for (int o = 16; o; o >>= 1) r += __shfl_xor_sync(0xffffffffu, r, o);
        if (lane == 0) sbuf[0] = r;
    }
    __syncthreads();
    float out = sbuf[0];
    __syncthreads();
    return out;
}

__device__ __forceinline__ float blk_max(float v, float* sbuf) {
    int lane = threadIdx.x & 31, w = threadIdx.x >> 5;
    int nw = blockDim.x >> 5;
#pragma unroll
    for (int o = 16; o; o >>= 1) v = fmaxf(v, __shfl_xor_sync(0xffffffffu, v, o));
    if (lane == 0) sbuf[w] = v;
    __syncthreads();
    float r = (threadIdx.x < nw) ? sbuf[threadIdx.x] : -INFINITY;
    if (w == 0) {
#pragma unroll
        for (int o = 16; o; o >>= 1) r = fmaxf(r, __shfl_xor_sync(0xffffffffu, r, o));
        if (lane == 0) sbuf[0] = r;
    }
    __syncthreads();
    float out = sbuf[0];
    __syncthreads();
    return out;
}

__device__ __forceinline__ float siluf(float x) { return x / (1.f + expf(-x)); }

// ------------------------- tiled fp32 GEMM: C[M,N] = act(A[M,K] @ W[N,K]^T + bias) (+C)
// BM=BN=64, BK=16, 256 threads, 4x4 microtile. M multiple of 64, K multiple of 16.
__global__ void gemm_nt(const float* __restrict__ A, const float* __restrict__ W,
                        const float* __restrict__ bias, float* __restrict__ C,
                        int N, int K, int act, int residual)
{
    __shared__ float As[16][64];
    __shared__ float Ws[16][64];
    int tid = threadIdx.x;
    int tx = tid & 15, ty = tid >> 4;
    int row0 = blockIdx.y * 64;
    int col0 = blockIdx.x * 64;
    int lr = tid >> 2;          // 0..63
    int lc = (tid & 3) * 4;     // 0,4,8,12

    float acc[4][4];
#pragma unroll
    for (int i = 0; i < 4; i++)
#pragma unroll
        for (int j = 0; j < 4; j++) acc[i][j] = 0.f;

    for (int k0 = 0; k0 < K; k0 += 16) {
        float4 av = *(const float4*)(A + (size_t)(row0 + lr) * K + k0 + lc);
        float4 wv;
        int wrow = col0 + lr;
        if (wrow < N) wv = *(const float4*)(W + (size_t)wrow * K + k0 + lc);
        else          wv = make_float4(0.f, 0.f, 0.f, 0.f);
        __syncthreads();
        As[(lc + 0) & 15][lr] = av.x; As[(lc + 1) & 15][lr] = av.y;
        As[(lc + 2) & 15][lr] = av.z; As[(lc + 3) & 15][lr] = av.w;
        Ws[(lc + 0) & 15][lr] = wv.x; Ws[(lc + 1) & 15][lr] = wv.y;
        Ws[(lc + 2) & 15][lr] = wv.z; Ws[(lc + 3) & 15][lr] = wv.w;
        __syncthreads();
#pragma unroll
        for (int kk = 0; kk < 16; kk++) {
            float4 a4 = *(const float4*)&As[kk][ty * 4];
            float4 b4 = *(const float4*)&Ws[kk][tx * 4];
            float aa[4] = {a4.x, a4.y, a4.z, a4.w};
            float bb[4] = {b4.x, b4.y, b4.z, b4.w};
#pragma unroll
            for (int i = 0; i < 4; i++)
#pragma unroll
                for (int j = 0; j < 4; j++)
                    acc[i][j] = fmaf(aa[i], bb[j], acc[i][j]);
        }
    }

#pragma unroll
    for (int i = 0; i < 4; i++) {
        int r = row0 + ty * 4 + i;
#pragma unroll
        for (int j = 0; j < 4; j++) {
            int c = col0 + tx * 4 + j;
            if (c < N) {
                float v = acc[i][j];
                if (bias) v += bias[c];
                if (act == 1) v = fmaxf(v, 0.f);
                else if (act == 2) v = tanhf(v);
                if (residual) v += C[(size_t)r * N + c];
                C[(size_t)r * N + c] = v;
            }
        }
    }
}

// ------------------------- layernorm: out = (x-mu)*rsqrt(var+eps)*w + b, rows of 512
__global__ void layernorm_k(const float* __restrict__ in, const float* __restrict__ w,
                            const float* __restrict__ b, float* __restrict__ out)
{
    __shared__ float sbuf[8];
    int t = blockIdx.x, tid = threadIdx.x; // 256 threads
    float2 v = ((const float2*)(in + (size_t)t * DM))[tid];
    float s  = v.x + v.y;
    float sq = v.x * v.x + v.y * v.y;
    float sum  = blk_sum(s, sbuf);
    float sumq = blk_sum(sq, sbuf);
    float mu  = sum * (1.f / DM);
    float var = sumq * (1.f / DM) - mu * mu;
    float rstd = rsqrtf(var + EPSV);
    float2 wv = ((const float2*)w)[tid];
    float2 bv = ((const float2*)b)[tid];
    float2 o;
    o.x = (v.x - mu) * rstd * wv.x + bv.x;
    o.y = (v.y - mu) * rstd * wv.y + bv.y;
    ((float2*)(out + (size_t)t * DM))[tid] = o;
}

// ------------------------- causal depthwise conv (K=4) + silu on xBC slice of g_zx
__global__ void conv_silu(const float* __restrict__ cw, const float* __restrict__ cb)
{
    int c = blockIdx.x * blockDim.x + threadIdx.x; // < 2560
    int t = blockIdx.y;
    float v = cb[c];
#pragma unroll
    for (int k = 0; k < 4; k++) {
        int tt = t + k - 3;
        if (tt >= 0) v = fmaf(g_zx[(size_t)tt * DPROJ + DIN + c], cw[c * 4 + k], v);
    }
    g_xbc[(size_t)t * CONVD + c] = siluf(v);
}

// ------------------------- dt = softplus(zx[..., -32:] + dt_bias)
__global__ void dt_kernel(const float* __restrict__ dtb)
{
    int idx = blockIdx.x * blockDim.x + threadIdx.x; // < L*NH
    int t = idx >> 5, h = idx & 31;
    float u = g_zx[(size_t)t * DPROJ + (DPROJ - NH) + h] + dtb[h];
    g_dt[idx] = (u > 20.f) ? u : log1pf(expf(u));
}

// ------------------------- sequential SSD scan, one CTA per head -----------
// thread (p,q): p=tid>>2 (headdim row), q=tid&3 (state-col quarter); 64 state regs.
__global__ void __launch_bounds__(256, 1)
scan_kernel(const float* __restrict__ A_log, const float* __restrict__ Dv)
{
    __shared__ float4 sB4[64];
    __shared__ float4 sC4[64];
    __shared__ float  sX[64];
    float* sB = (float*)sB4;
    float* sC = (float*)sC4;

    int h = blockIdx.x;
    int tid = threadIdx.x;
    int p = tid >> 2, q = tid & 3;
    float A  = -expf(A_log[h]);
    float Dh = Dv[h];

    float st[64];
#pragma unroll
    for (int i = 0; i < 64; i++) st[i] = 0.f;

    // swizzled store slot for element n = tid: makes compute-side float4 reads conflict-free
    int jj = tid & 63, qq = tid >> 6;
    int sw = (jj >> 2) * 16 + qq * 4 + (jj & 3);

    // prefetch t=0
    const float* r0 = g_xbc;
    float rB = r0[DIN + tid];
    float rC = r0[DIN + DSTATE + tid];
    float rX = (tid < 64) ? r0[h * HD + tid] : 0.f;
    float rdt = g_dt[h];

    for (int t = 0; t < L; t++) {
        __syncthreads();                    // previous step's smem fully consumed
        sB[sw] = rB;
        sC[sw] = rC;
        if (tid < 64) sX[tid] = rX;
        float dt_t = rdt;
        if (t + 1 < L) {                    // prefetch next step (hidden behind compute)
            const float* nr = g_xbc + (size_t)(t + 1) * CONVD;
            rB = nr[DIN + tid];
            rC = nr[DIN + DSTATE + tid];
            if (tid < 64) rX = nr[h * HD + tid];
            rdt = g_dt[(t + 1) * NH + h];
        }
        __syncthreads();

        float decay = expf(dt_t * A);
        float xp = sX[p];
        float xs = dt_t * xp;
        float acc = 0.f;
#pragma unroll
        for (int g = 0; g < 16; g++) {
            float4 b4 = sB4[g * 4 + q];
            float4 c4 = sC4[g * 4 + q];
            float s0 = fmaf(xs, b4.x, st[4 * g + 0] * decay);
            float s1 = fmaf(xs, b4.y, st[4 * g + 1] * decay);
            float s2 = fmaf(xs, b4.z, st[4 * g + 2] * decay);
            float s3 = fmaf(xs, b4.w, st[4 * g + 3] * decay);
            st[4 * g + 0] = s0; st[4 * g + 1] = s1;
            st[4 * g + 2] = s2; st[4 * g + 3] = s3;
            acc = fmaf(s0, c4.x, acc);
            acc = fmaf(s1, c4.y, acc);
            acc = fmaf(s2, c4.z, acc);
            acc = fmaf(s3, c4.w, acc);
        }
        acc += __shfl_xor_sync(0xffffffffu, acc, 1);
        acc += __shfl_xor_sync(0xffffffffu, acc, 2);
        if (q == 0) g_y[(size_t)t * DIN + h * HD + p] = fmaf(Dh, xp, acc);
    }
}

// ------------------------- y *= silu(z); rmsnorm * rms_w -------------------
__global__ void gate_rms(const float* __restrict__ rmsw)
{
    __shared__ float sbuf[8];
    int t = blockIdx.x, tid = threadIdx.x; // 256 threads, 8 elems each
    float ry[8];
    float ss = 0.f;
#pragma unroll
    for (int i = 0; i < 8; i++) {
        int e = tid + i * 256;
        float z = g_zx[(size_t)t * DPROJ + e];
        float yv = g_y[(size_t)t * DIN + e] * siluf(z);
        ry[i] = yv;
        ss += yv * yv;
    }
    float tot = blk_sum(ss, sbuf);
    float scale = rsqrtf(tot * (1.f / DIN) + EPSV);
#pragma unroll
    for (int i = 0; i < 8; i++) {
        int e = tid + i * 256;
        g_yn[(size_t)t * DIN + e] = ry[i] * scale * rmsw[e];
    }
}

// ------------------------- attention logit per row: s1[row]·w2 + b2 --------
__global__ void alog_kernel(const float* __restrict__ w2, const float* __restrict__ b2)
{
    int warp = threadIdx.x >> 5, lane = threadIdx.x & 31;
    int row = blockIdx.x * 8 + warp;
    float s = 0.f;
#pragma unroll
    for (int i = 0; i < 4; i++)
        s = fmaf(g_s1[(size_t)row * 128 + lane + i * 32], w2[lane + i * 32], s);
#pragma unroll
    for (int o = 16; o; o >>= 1) s += __shfl_xor_sync(0xffffffffu, s, o);
    if (lane == 0) g_alog[row] = s + b2[0];
}

// ------------------------- softmax over L (single block) -------------------
__global__ void softmax_l()
{
    __shared__ float sbuf[32];
    int tid = threadIdx.x; // 1024
    float v[4], e[4];
    float mx = -INFINITY;
#pragma unroll
    for (int i = 0; i < 4; i++) { v[i] = g_alog[tid + i * 1024]; mx = fmaxf(mx, v[i]); }
    mx = blk_max(mx, sbuf);
    float s = 0.f;
#pragma unroll
    for (int i = 0; i < 4; i++) { e[i] = expf(v[i] - mx); s += e[i]; }
    s = blk_sum(s, sbuf);
    float inv = 1.f / s;
#pragma unroll
    for (int i = 0; i < 4; i++) g_att[tid + i * 1024] = e[i] * inv;
}

// ------------------------- pooled partials: block b sums 128 rows ----------
__global__ void pooled_part()
{
    int b = blockIdx.x, tid = threadIdx.x; // 512 threads
    float acc = 0.f;
    for (int tt = 0; tt < 128; tt++) {
        int t = b * 128 + tt;
        acc = fmaf(g_att[t], g_hn[(size_t)t * DM + tid], acc);
    }
    g_part[b * DM + tid] = acc;
}

// ------------------------- final: pooled -> logits/probs/argmax ------------
__global__ void finalize_kernel(const float* __restrict__ cls_w, const float* __restrict__ cls_b,
                                float* __restrict__ out, int out_size)
{
    __shared__ float spool[DM];
    __shared__ float slog[4];
    int tid = threadIdx.x; // 512
    float acc = 0.f;
#pragma unroll
    for (int b = 0; b < 32; b++) acc += g_part[b * DM + tid];
    spool[tid] = acc;
    __syncthreads();
    int w = tid >> 5, lane = tid & 31;
    if (w < 4) {
        float s = 0.f;
#pragma unroll
        for (int i = 0; i < 16; i++)
            s = fmaf(spool[lane + i * 32], cls_w[w * DM + lane + i * 32], s);
#pragma unroll
        for (int o = 16; o; o >>= 1) s += __shfl_xor_sync(0xffffffffu, s, o);
        if (lane == 0) slog[w] = s + cls_b[w];
    }
    __syncthreads();
    if (tid == 0) {
        float l[4] = {slog[0], slog[1], slog[2], slog[3]};
        float mx = fmaxf(fmaxf(l[0], l[1]), fmaxf(l[2], l[3]));
        float e[4], s = 0.f;
#pragma unroll
        for (int c = 0; c < 4; c++) { e[c] = expf(l[c] - mx); s += e[c]; }
        int am = 0;
#pragma unroll
        for (int c = 1; c < 4; c++) if (l[c] > l[am]) am = c;
        if (out_size >= 4) { out[0] = l[0]; out[1] = l[1]; out[2] = l[2]; out[3] = l[3]; }
        if (out_size >= 8) { for (int c = 0; c < 4; c++) out[4 + c] = e[c] / s; }
        if (out_size >= 9) out[8] = (float)am;
    }
}

// ===========================================================================
extern "C" void kernel_launch(void* const* d_in, const int* in_sizes, int n_in,
                              void* d_out, int out_size)
{
    const float* x        = (const float*)d_in[0];
    const float* fc1_w    = (const float*)d_in[1];
    const float* fc1_b    = (const float*)d_in[2];
    const float* ln_w     = (const float*)d_in[3];
    const float* ln_b     = (const float*)d_in[4];
    const float* in_proj  = (const float*)d_in[5];
    const float* conv_w   = (const float*)d_in[6];
    const float* conv_b   = (const float*)d_in[7];
    const float* dt_bias  = (const float*)d_in[8];
    const float* A_log    = (const float*)d_in[9];
    const float* Dvec     = (const float*)d_in[10];
    const float* rms_w    = (const float*)d_in[11];
    const float* out_proj = (const float*)d_in[12];
    const float* norm_w   = (const float*)d_in[13];
    const float* norm_b   = (const float*)d_in[14];
    const float* att_w1   = (const float*)d_in[15];
    const float* att_b1   = (const float*)d_in[16];
    const float* att_w2   = (const float*)d_in[17];
    const float* att_b2   = (const float*)d_in[18];
    const float* cls_w    = (const float*)d_in[19];
    const float* cls_b    = (const float*)d_in[20];
    float* out = (float*)d_out;

    float *h, *hn, *zx, *yn, *s1;
    cudaGetSymbolAddress((void**)&h,  g_h);
    cudaGetSymbolAddress((void**)&hn, g_hn);
    cudaGetSymbolAddress((void**)&zx, g_zx);
    cudaGetSymbolAddress((void**)&yn, g_yn);
    cudaGetSymbolAddress((void**)&s1, g_s1);

    // h = relu(x @ fc1_w^T + fc1_b)
    gemm_nt<<<dim3(DM / 64, L / 64), 256>>>(x, fc1_w, fc1_b, h, DM, INDIM, 1, 0);

    for (int layer = 0; layer < 2; layer++) {
        layernorm_k<<<L, 256>>>(h, ln_w + layer * DM, ln_b + layer * DM, hn);
        gemm_nt<<<dim3((DPROJ + 63) / 64, L / 64), 256>>>(
            hn, in_proj + (size_t)layer * DPROJ * DM, nullptr, zx, DPROJ, DM, 0, 0);
        conv_silu<<<dim3(CONVD / 256, L), 256>>>(conv_w + layer * CONVD * 4,
                                                 conv_b + layer * CONVD);
        dt_kernel<<<(L * NH) / 256, 256>>>(dt_bias + layer * NH);
        scan_kernel<<<NH, 256>>>(A_log + layer * NH, Dvec + layer * NH);
        gate_rms<<<L, 256>>>(rms_w + layer * DIN);
        gemm_nt<<<dim3(DM / 64, L / 64), 256>>>(
            yn, out_proj + (size_t)layer * DM * DIN, nullptr, h, DM, DIN, 0, 1);
    }

    layernorm_k<<<L, 256>>>(h, norm_w, norm_b, hn);
    gemm_nt<<<dim3(128 / 64, L / 64), 256>>>(hn, att_w1, att_b1, s1, 128, DM, 2, 0);
    alog_kernel<<<L / 8, 256>>>(att_w2, att_b2);
    softmax_l<<<1, 1024>>>();
    pooled_part<<<32, 512>>>();
    finalize_kernel<<<1, 512>>>(cls_w, cls_b, out, out_size);
}

// round 2
// speedup vs baseline: 1.2362x; 1.2362x over previous
#include <cuda_runtime.h>
#include <math.h>

#define L       4096
#define INDIM   1024
#define DM      512
#define DIN     2048
#define DSTATE  256
#define CONVD   2560
#define DPROJ   4640
#define NH      32
#define HD      64
#define EPSV    1e-5f
#define SPLIT   4

typedef unsigned long long ull;

// ------------------------- packed f32x2 helpers ---------------------------
__device__ __forceinline__ ull pk2(float x, float y) {
    ull r; asm("mov.b64 %0,{%1,%2};" : "=l"(r) : "f"(x), "f"(y)); return r;
}
__device__ __forceinline__ float2 upk(ull v) {
    float2 f; asm("mov.b64 {%0,%1},%2;" : "=f"(f.x), "=f"(f.y) : "l"(v)); return f;
}
__device__ __forceinline__ ull ffma2(ull a, ull b, ull c) {
    ull r; asm("fma.rn.f32x2 %0,%1,%2,%3;" : "=l"(r) : "l"(a), "l"(b), "l"(c)); return r;
}
__device__ __forceinline__ ull fmul2(ull a, ull b) {
    ull r; asm("mul.rn.f32x2 %0,%1,%2;" : "=l"(r) : "l"(a), "l"(b)); return r;
}

// ------------------------- scratch (device globals; no allocs allowed) ----
__device__ __align__(256) float g_h  [L * DM];
__device__ __align__(256) float g_hn [L * DM];
__device__ __align__(256) float g_zx [(size_t)L * DPROJ];
__device__ __align__(256) float g_xbc[(size_t)L * CONVD];
__device__ __align__(256) float g_dt [L * NH];
__device__ __align__(256) float g_yp [SPLIT][(size_t)L * DIN];
__device__ __align__(256) float g_yn [(size_t)L * DIN];
__device__ __align__(256) float g_s1 [L * 128];
__device__ __align__(256) float g_alog[L];
__device__ __align__(256) float g_att [L];
__device__ __align__(256) float g_part[32 * DM];

// ------------------------- helpers ---------------------------------------
__device__ __forceinline__ float blk_sum(float v, float* sbuf) {
    int lane = threadIdx.x & 31, w = threadIdx.x >> 5;
    int nw = blockDim.x >> 5;
#pragma unroll
    for (int o = 16; o; o >>= 1) v += __shfl_xor_sync(0xffffffffu, v, o);
    if (lane == 0) sbuf[w] = v;
    __syncthreads();
    float r = (threadIdx.x < nw) ? sbuf[threadIdx.x] : 0.f;
    if (w == 0) {
#pragma unroll
        for (int o = 16; o; o >>= 1) r += __shfl_xor_sync(0xffffffffu, r, o);
        if (lane == 0) sbuf[0] = r;
    }
    __syncthreads();
    float out = sbuf[0];
    __syncthreads();
    return out;
}

__device__ __forceinline__ float blk_max(float v, float* sbuf) {
    int lane = threadIdx.x & 31, w = threadIdx.x >> 5;
    int nw = blockDim.x >> 5;
#pragma unroll
    for (int o = 16; o; o >>= 1) v = fmaxf(v, __shfl_xor_sync(0xffffffffu, v, o));
    if (lane == 0) sbuf[w] = v;
    __syncthreads();
    float r = (threadIdx.x < nw) ? sbuf[threadIdx.x] : -INFINITY;
    if (w == 0) {
#pragma unroll
        for (int o = 16; o; o >>= 1) r = fmaxf(r, __shfl_xor_sync(0xffffffffu, r, o));
        if (lane == 0) sbuf[0] = r;
    }
    __syncthreads();
    float out = sbuf[0];
    __syncthreads();
    return out;
}

__device__ __forceinline__ float siluf(float x) { return x / (1.f + __expf(-x)); }

// ------------------------- tiled fp32 GEMM (f32x2 packed math) ------------
// C[M,N] = act(A[M,K] @ W[N,K]^T + bias) (+C). BM=BN=64, BK=16, 256 thr, 4x4 microtile.
__global__ void __launch_bounds__(256)
gemm_nt(const float* __restrict__ A, const float* __restrict__ W,
        const float* __restrict__ bias, float* __restrict__ C,
        int N, int K, int act, int residual)
{
    __shared__ float As[16][64];
    __shared__ float Ws[16][64];
    int tid = threadIdx.x;
    int tx = tid & 15, ty = tid >> 4;
    int row0 = blockIdx.y * 64;
    int col0 = blockIdx.x * 64;
    int lr = tid >> 2;          // 0..63
    int lc = (tid & 3) * 4;     // 0,4,8,12

    ull acc2[4][2];
#pragma unroll
    for (int i = 0; i < 4; i++) { acc2[i][0] = 0ull; acc2[i][1] = 0ull; }

    for (int k0 = 0; k0 < K; k0 += 16) {
        float4 av = *(const float4*)(A + (size_t)(row0 + lr) * K + k0 + lc);
        float4 wv;
        int wrow = col0 + lr;
        if (wrow < N) wv = *(const float4*)(W + (size_t)wrow * K + k0 + lc);
        else          wv = make_float4(0.f, 0.f, 0.f, 0.f);
        __syncthreads();
        As[(lc + 0) & 15][lr] = av.x; As[(lc + 1) & 15][lr] = av.y;
        As[(lc + 2) & 15][lr] = av.z; As[(lc + 3) & 15][lr] = av.w;
        Ws[(lc + 0) & 15][lr] = wv.x; Ws[(lc + 1) & 15][lr] = wv.y;
        Ws[(lc + 2) & 15][lr] = wv.z; Ws[(lc + 3) & 15][lr] = wv.w;
        __syncthreads();
#pragma unroll
        for (int kk = 0; kk < 16; kk++) {
            float4 a4 = *(const float4*)&As[kk][ty * 4];
            float4 b4 = *(const float4*)&Ws[kk][tx * 4];
            ull b01 = pk2(b4.x, b4.y);
            ull b23 = pk2(b4.z, b4.w);
            float aa[4] = {a4.x, a4.y, a4.z, a4.w};
#pragma unroll
            for (int i = 0; i < 4; i++) {
                ull ai = pk2(aa[i], aa[i]);
                acc2[i][0] = ffma2(ai, b01, acc2[i][0]);
                acc2[i][1] = ffma2(ai, b23, acc2[i][1]);
            }
        }
    }

#pragma unroll
    for (int i = 0; i < 4; i++) {
        int r = row0 + ty * 4 + i;
        float2 v01 = upk(acc2[i][0]);
        float2 v23 = upk(acc2[i][1]);
        float vals[4] = {v01.x, v01.y, v23.x, v23.y};
#pragma unroll
        for (int j = 0; j < 4; j++) {
            int c = col0 + tx * 4 + j;
            if (c < N) {
                float v = vals[j];
                if (bias) v += bias[c];
                if (act == 1) v = fmaxf(v, 0.f);
                else if (act == 2) v = tanhf(v);
                if (residual) v += C[(size_t)r * N + c];
                C[(size_t)r * N + c] = v;
            }
        }
    }
}

// ------------------------- layernorm -------------------------------------
__global__ void layernorm_k(const float* __restrict__ in, const float* __restrict__ w,
                            const float* __restrict__ b, float* __restrict__ out)
{
    __shared__ float sbuf[8];
    int t = blockIdx.x, tid = threadIdx.x; // 256 threads
    float2 v = ((const float2*)(in + (size_t)t * DM))[tid];
    float s  = v.x + v.y;
    float sq = v.x * v.x + v.y * v.y;
    float sum  = blk_sum(s, sbuf);
    float sumq = blk_sum(sq, sbuf);
    float mu  = sum * (1.f / DM);
    float var = sumq * (1.f / DM) - mu * mu;
    float rstd = rsqrtf(var + EPSV);
    float2 wv = ((const float2*)w)[tid];
    float2 bv = ((const float2*)b)[tid];
    float2 o;
    o.x = (v.x - mu) * rstd * wv.x + bv.x;
    o.y = (v.y - mu) * rstd * wv.y + bv.y;
    ((float2*)(out + (size_t)t * DM))[tid] = o;
}

// ------------------------- causal depthwise conv (K=4) + silu -------------
__global__ void conv_silu(const float* __restrict__ cw, const float* __restrict__ cb)
{
    int c = blockIdx.x * blockDim.x + threadIdx.x; // < 2560
    int t = blockIdx.y;
    float v = cb[c];
#pragma unroll
    for (int k = 0; k < 4; k++) {
        int tt = t + k - 3;
        if (tt >= 0) v = fmaf(g_zx[(size_t)tt * DPROJ + DIN + c], cw[c * 4 + k], v);
    }
    g_xbc[(size_t)t * CONVD + c] = siluf(v);
}

// ------------------------- dt = softplus(zx[..., -32:] + dt_bias) ---------
__global__ void dt_kernel(const float* __restrict__ dtb)
{
    int idx = blockIdx.x * blockDim.x + threadIdx.x; // < L*NH
    int t = idx >> 5, h = idx & 31;
    float u = g_zx[(size_t)t * DPROJ + (DPROJ - NH) + h] + dtb[h];
    g_dt[idx] = (u > 20.f) ? u : log1pf(expf(u));
}

// ------------------------- sequential SSD scan, state-split x4 ------------
// CTA (h, g4) owns headdim 64 x state cols [g4*64, g4*64+64).
// thread: p = tid>>2 (headdim row), q = tid&3 (16 states = 8 f32x2 pairs).
// smem pair layout padded: pair m -> slot (m>>3)*9 + (m&7)  (conflict-free LDS.64)
__global__ void __launch_bounds__(256, 1)
scan_kernel(const float* __restrict__ A_log, const float* __restrict__ Dv)
{
    __shared__ ull  sB2[40];
    __shared__ ull  sC2[40];
    __shared__ float sX[64];
    __shared__ float sdt;

    int bx = blockIdx.x;
    int h = bx >> 2, g4 = bx & 3;
    int tid = threadIdx.x;
    int p = tid >> 2, q = tid & 3;
    float A  = -expf(A_log[h]);
    float Dh = Dv[h];
    int base = g4 * 64;

    ull st[8];
#pragma unroll
    for (int i = 0; i < 8; i++) st[i] = 0ull;

    // prefetch t=0 (loader roles by tid range)
    float rv = 0.f, rx = 0.f, rdt = 0.f;
    {
        const float* r0 = g_xbc;
        if (tid < 64)        rv = r0[DIN + base + tid];
        else if (tid < 128)  rv = r0[DIN + DSTATE + base + (tid - 64)];
        else if (tid < 192)  rx = r0[h * HD + (tid - 128)];
        if (tid == 192)      rdt = g_dt[h];
    }

    float* out0 = &g_yp[g4][0];

    for (int t = 0; t < L; t++) {
        __syncthreads();                    // previous step's smem fully consumed
        if (tid < 64) {
            int m = tid >> 1;
            ((float*)sB2)[((m >> 3) * 9 + (m & 7)) * 2 + (tid & 1)] = rv;
        } else if (tid < 128) {
            int u = tid - 64; int m = u >> 1;
            ((float*)sC2)[((m >> 3) * 9 + (m & 7)) * 2 + (u & 1)] = rv;
        } else if (tid < 192) {
            sX[tid - 128] = rx;
        }
        if (tid == 192) sdt = rdt;
        if (t + 1 < L) {                    // prefetch next step
            const float* nr = g_xbc + (size_t)(t + 1) * CONVD;
            if (tid < 64)        rv = nr[DIN + base + tid];
            else if (tid < 128)  rv = nr[DIN + DSTATE + base + (tid - 64)];
            else if (tid < 192)  rx = nr[h * HD + (tid - 128)];
            if (tid == 192)      rdt = g_dt[(t + 1) * NH + h];
        }
        __syncthreads();

        float dt_t = sdt;
        float dec  = __expf(dt_t * A);
        float xp   = sX[p];
        float xs   = dt_t * xp;
        ull dec2 = pk2(dec, dec);
        ull xs2  = pk2(xs, xs);
        ull acc2 = 0ull;
#pragma unroll
        for (int j = 0; j < 8; j++) {
            ull b2 = sB2[q * 9 + j];
            ull c2 = sC2[q * 9 + j];
            st[j] = ffma2(xs2, b2, fmul2(st[j], dec2));
            acc2  = ffma2(st[j], c2, acc2);
        }
        float2 af = upk(acc2);
        float acc = af.x + af.y;
        acc += __shfl_xor_sync(0xffffffffu, acc, 1);
        acc += __shfl_xor_sync(0xffffffffu, acc, 2);
        if (q == 0) {
            float outv = acc;
            if (g4 == 0) outv = fmaf(Dh, xp, outv);
            out0[(size_t)t * DIN + h * HD + p] = outv;
        }
    }
}

// ------------------------- y = sum(partials); y *= silu(z); rmsnorm -------
__global__ void gate_rms(const float* __restrict__ rmsw)
{
    __shared__ float sbuf[8];
    int t = blockIdx.x, tid = threadIdx.x; // 256 threads, 8 elems each
    float ry[8];
    float ss = 0.f;
#pragma unroll
    for (int i = 0; i < 8; i++) {
        int e = tid + i * 256;
        size_t idx = (size_t)t * DIN + e;
        float z  = g_zx[(size_t)t * DPROJ + e];
        float yv = (g_yp[0][idx] + g_yp[1][idx] + g_yp[2][idx] + g_yp[3][idx]) * siluf(z);
        ry[i] = yv;
        ss += yv * yv;
    }
    float tot = blk_sum(ss, sbuf);
    float scale = rsqrtf(tot * (1.f / DIN) + EPSV);
#pragma unroll
    for (int i = 0; i < 8; i++) {
        int e = tid + i * 256;
        g_yn[(size_t)t * DIN + e] = ry[i] * scale * rmsw[e];
    }
}

// ------------------------- attention logit per row ------------------------
__global__ void alog_kernel(const float* __restrict__ w2, const float* __restrict__ b2)
{
    int warp = threadIdx.x >> 5, lane = threadIdx.x & 31;
    int row = blockIdx.x * 8 + warp;
    float s = 0.f;
#pragma unroll
    for (int i = 0; i < 4; i++)
        s = fmaf(g_s1[(size_t)row * 128 + lane + i * 32], w2[lane + i * 32], s);
#pragma unroll
    for (int o = 16; o; o >>= 1) s += __shfl_xor_sync(0xffffffffu, s, o);
    if (lane == 0) g_alog[row] = s + b2[0];
}

// ------------------------- softmax over L (single block) ------------------
__global__ void softmax_l()
{
    __shared__ float sbuf[32];
    int tid = threadIdx.x; // 1024
    float v[4], e[4];
    float mx = -INFINITY;
#pragma unroll
    for (int i = 0; i < 4; i++) { v[i] = g_alog[tid + i * 1024]; mx = fmaxf(mx, v[i]); }
    mx = blk_max(mx, sbuf);
    float s = 0.f;
#pragma unroll
    for (int i = 0; i < 4; i++) { e[i] = expf(v[i] - mx); s += e[i]; }
    s = blk_sum(s, sbuf);
    float inv = 1.f / s;
#pragma unroll
    for (int i = 0; i < 4; i++) g_att[tid + i * 1024] = e[i] * inv;
}

// ------------------------- pooled partials --------------------------------
__global__ void pooled_part()
{
    int b = blockIdx.x, tid = threadIdx.x; // 512 threads
    float acc = 0.f;
    for (int tt = 0; tt < 128; tt++) {
        int t = b * 128 + tt;
        acc = fmaf(g_att[t], g_hn[(size_t)t * DM + tid], acc);
    }
    g_part[b * DM + tid] = acc;
}

// ------------------------- final ------------------------------------------
__global__ void finalize_kernel(const float* __restrict__ cls_w, const float* __restrict__ cls_b,
                                float* __restrict__ out, int out_size)
{
    __shared__ float spool[DM];
    __shared__ float slog[4];
    int tid = threadIdx.x; // 512
    float acc = 0.f;
#pragma unroll
    for (int b = 0; b < 32; b++) acc += g_part[b * DM + tid];
    spool[tid] = acc;
    __syncthreads();
    int w = tid >> 5, lane = tid & 31;
    if (w < 4) {
        float s = 0.f;
#pragma unroll
        for (int i = 0; i < 16; i++)
            s = fmaf(spool[lane + i * 32], cls_w[w * DM + lane + i * 32], s);
#pragma unroll
        for (int o = 16; o; o >>= 1) s += __shfl_xor_sync(0xffffffffu, s, o);
        if (lane == 0) slog[w] = s + cls_b[w];
    }
    __syncthreads();
    if (tid == 0) {
        float l[4] = {slog[0], slog[1], slog[2], slog[3]};
        float mx = fmaxf(fmaxf(l[0], l[1]), fmaxf(l[2], l[3]));
        float e[4], s = 0.f;
#pragma unroll
        for (int c = 0; c < 4; c++) { e[c] = expf(l[c] - mx); s += e[c]; }
        int am = 0;
#pragma unroll
        for (int c = 1; c < 4; c++) if (l[c] > l[am]) am = c;
        if (out_size >= 4) { out[0] = l[0]; out[1] = l[1]; out[2] = l[2]; out[3] = l[3]; }
        if (out_size >= 8) { for (int c = 0; c < 4; c++) out[4 + c] = e[c] / s; }
        if (out_size >= 9) out[8] = (float)am;
    }
}

// ===========================================================================
extern "C" void kernel_launch(void* const* d_in, const int* in_sizes, int n_in,
                              void* d_out, int out_size)
{
    const float* x        = (const float*)d_in[0];
    const float* fc1_w    = (const float*)d_in[1];
    const float* fc1_b    = (const float*)d_in[2];
    const float* ln_w     = (const float*)d_in[3];
    const float* ln_b     = (const float*)d_in[4];
    const float* in_proj  = (const float*)d_in[5];
    const float* conv_w   = (const float*)d_in[6];
    const float* conv_b   = (const float*)d_in[7];
    const float* dt_bias  = (const float*)d_in[8];
    const float* A_log    = (const float*)d_in[9];
    const float* Dvec     = (const float*)d_in[10];
    const float* rms_w    = (const float*)d_in[11];
    const float* out_proj = (const float*)d_in[12];
    const float* norm_w   = (const float*)d_in[13];
    const float* norm_b   = (const float*)d_in[14];
    const float* att_w1   = (const float*)d_in[15];
    const float* att_b1   = (const float*)d_in[16];
    const float* att_w2   = (const float*)d_in[17];
    const float* att_b2   = (const float*)d_in[18];
    const float* cls_w    = (const float*)d_in[19];
    const float* cls_b    = (const float*)d_in[20];
    float* out = (float*)d_out;

    float *h, *hn, *zx, *yn, *s1;
    cudaGetSymbolAddress((void**)&h,  g_h);
    cudaGetSymbolAddress((void**)&hn, g_hn);
    cudaGetSymbolAddress((void**)&zx, g_zx);
    cudaGetSymbolAddress((void**)&yn, g_yn);
    cudaGetSymbolAddress((void**)&s1, g_s1);

    // h = relu(x @ fc1_w^T + fc1_b)
    gemm_nt<<<dim3(DM / 64, L / 64), 256>>>(x, fc1_w, fc1_b, h, DM, INDIM, 1, 0);

    for (int layer = 0; layer < 2; layer++) {
        layernorm_k<<<L, 256>>>(h, ln_w + layer * DM, ln_b + layer * DM, hn);
        gemm_nt<<<dim3((DPROJ + 63) / 64, L / 64), 256>>>(
            hn, in_proj + (size_t)layer * DPROJ * DM, nullptr, zx, DPROJ, DM, 0, 0);
        conv_silu<<<dim3(CONVD / 256, L), 256>>>(conv_w + layer * CONVD * 4,
                                                 conv_b + layer * CONVD);
        dt_kernel<<<(L * NH) / 256, 256>>>(dt_bias + layer * NH);
        scan_kernel<<<NH * SPLIT, 256>>>(A_log + layer * NH, Dvec + layer * NH);
        gate_rms<<<L, 256>>>(rms_w + layer * DIN);
        gemm_nt<<<dim3(DM / 64, L / 64), 256>>>(
            yn, out_proj + (size_t)layer * DM * DIN, nullptr, h, DM, DIN, 0, 1);
    }

    layernorm_k<<<L, 256>>>(h, norm_w, norm_b, hn);
    gemm_nt<<<dim3(128 / 64, L / 64), 256>>>(hn, att_w1, att_b1, s1, 128, DM, 2, 0);
    alog_kernel<<<L / 8, 256>>>(att_w2, att_b2);
    softmax_l<<<1, 1024>>>();
    pooled_part<<<32, 512>>>();
    finalize_kernel<<<1, 512>>>(cls_w, cls_b, out, out_size);
}

// round 4
// speedup vs baseline: 2.4251x; 1.9618x over previous
#include <cuda_runtime.h>
#include <math.h>

#define L       4096
#define INDIM   1024
#define DM      512
#define DIN     2048
#define DSTATE  256
#define CONVD   2560
#define DPROJ   4640
#define NH      32
#define HD      64
#define EPSV    1e-5f
#define SPLIT   4
#define TC      16          // scan chunk length
#define NC      (L / TC)

typedef unsigned long long ull;

// ------------------------- packed f32x2 helpers ---------------------------
__device__ __forceinline__ ull pk2(float x, float y) {
    ull r; asm("mov.b64 %0,{%1,%2};" : "=l"(r) : "f"(x), "f"(y)); return r;
}
__device__ __forceinline__ float2 upk(ull v) {
    float2 f; asm("mov.b64 {%0,%1},%2;" : "=f"(f.x), "=f"(f.y) : "l"(v)); return f;
}
__device__ __forceinline__ ull ffma2(ull a, ull b, ull c) {
    ull r; asm("fma.rn.f32x2 %0,%1,%2,%3;" : "=l"(r) : "l"(a), "l"(b), "l"(c)); return r;
}
__device__ __forceinline__ ull fmul2(ull a, ull b) {
    ull r; asm("mul.rn.f32x2 %0,%1,%2;" : "=l"(r) : "l"(a), "l"(b)); return r;
}

// ------------------------- scratch ----------------------------------------
__device__ __align__(256) float g_h  [L * DM];
__device__ __align__(256) float g_hn [L * DM];
__device__ __align__(256) float g_zx [(size_t)L * DPROJ];
__device__ __align__(256) float g_xbc[(size_t)L * CONVD];
__device__ __align__(256) float g_dt [L * NH];
__device__ __align__(256) float g_yp [SPLIT][(size_t)L * DIN];
__device__ __align__(256) float g_yn [(size_t)L * DIN];
__device__ __align__(256) float g_s1 [L * 128];
__device__ __align__(256) float g_alog[L];
__device__ __align__(256) float g_att [L];
__device__ __align__(256) float g_part[32 * DM];

// ------------------------- reductions -------------------------------------
__device__ __forceinline__ float blk_sum(float v, float* sbuf) {
    int lane = threadIdx.x & 31, w = threadIdx.x >> 5;
    int nw = blockDim.x >> 5;
#pragma unroll
    for (int o = 16; o; o >>= 1) v += __shfl_xor_sync(0xffffffffu, v, o);
    if (lane == 0) sbuf[w] = v;
    __syncthreads();
    float r = (threadIdx.x < nw) ? sbuf[threadIdx.x] : 0.f;
    if (w == 0) {
#pragma unroll
        for (int o = 16; o; o >>= 1) r += __shfl_xor_sync(0xffffffffu, r, o);
        if (lane == 0) sbuf[0] = r;
    }
    __syncthreads();
    float out = sbuf[0];
    __syncthreads();
    return out;
}

__device__ __forceinline__ float blk_max(float v, float* sbuf) {
    int lane = threadIdx.x & 31, w = threadIdx.x >> 5;
    int nw = blockDim.x >> 5;
#pragma unroll
    for (int o = 16; o; o >>= 1) v = fmaxf(v, __shfl_xor_sync(0xffffffffu, v, o));
    if (lane == 0) sbuf[w] = v;
    __syncthreads();
    float r = (threadIdx.x < nw) ? sbuf[threadIdx.x] : -INFINITY;
    if (w == 0) {
#pragma unroll
        for (int o = 16; o; o >>= 1) r = fmaxf(r, __shfl_xor_sync(0xffffffffu, r, o));
        if (lane == 0) sbuf[0] = r;
    }
    __syncthreads();
    float out = sbuf[0];
    __syncthreads();
    return out;
}

__device__ __forceinline__ float siluf(float x) { return x / (1.f + __expf(-x)); }

// ===========================================================================
// GEMM: C[M,N] = act(A[M,K] @ W[N,K]^T + bias) (+C)
// 128x128 tile, BK=16, 256 threads, 8x8 microtile, f32x2, double-buffered.
// M % 128 == 0, K % 16 == 0, N % 4 == 0.
// ===========================================================================
__global__ void __launch_bounds__(256)
gemm_nt(const float* __restrict__ A, const float* __restrict__ W,
        const float* __restrict__ bias, float* __restrict__ C,
        int N, int K, int act, int residual)
{
    __shared__ float As[2][16][128];
    __shared__ float Ws[2][16][128];
    int tid = threadIdx.x;
    int tx = tid & 15, ty = tid >> 4;
    int row0 = blockIdx.y * 128;
    int col0 = blockIdx.x * 128;
    int ar = tid >> 1;            // 0..127
    int aq = tid & 1;             // k-half: 0 or 8

    ull acc[8][4];
#pragma unroll
    for (int i = 0; i < 8; i++)
#pragma unroll
        for (int j = 0; j < 4; j++) acc[i][j] = 0ull;

    const float* Aip = A + (size_t)(row0 + ar) * K + aq * 8;
    int wrow = col0 + ar;
    const float* Wip = (wrow < N) ? (W + (size_t)wrow * K + aq * 8) : nullptr;

    float4 a0, a1, w0, w1;
    // initial tile
    a0 = *(const float4*)(Aip + 0);
    a1 = *(const float4*)(Aip + 4);
    if (Wip) { w0 = *(const float4*)(Wip + 0); w1 = *(const float4*)(Wip + 4); }
    else     { w0 = w1 = make_float4(0.f, 0.f, 0.f, 0.f); }
    {
        float av[8] = {a0.x, a0.y, a0.z, a0.w, a1.x, a1.y, a1.z, a1.w};
        float wv[8] = {w0.x, w0.y, w0.z, w0.w, w1.x, w1.y, w1.z, w1.w};
#pragma unroll
        for (int i = 0; i < 8; i++) { As[0][aq * 8 + i][ar] = av[i]; Ws[0][aq * 8 + i][ar] = wv[i]; }
    }
    __syncthreads();

    int nkt = K >> 4;
    for (int kt = 0; kt < nkt; kt++) {
        int b = kt & 1;
        if (kt + 1 < nkt) {
            const float* ap = Aip + (kt + 1) * 16;
            a0 = *(const float4*)(ap + 0);
            a1 = *(const float4*)(ap + 4);
            if (Wip) {
                const float* wp = Wip + (kt + 1) * 16;
                w0 = *(const float4*)(wp + 0);
                w1 = *(const float4*)(wp + 4);
            }
        }
#pragma unroll
        for (int kk = 0; kk < 16; kk++) {
            float4 A01 = *(const float4*)&As[b][kk][ty * 8];
            float4 A23 = *(const float4*)&As[b][kk][ty * 8 + 4];
            float4 B01 = *(const float4*)&Ws[b][kk][tx * 8];
            float4 B23 = *(const float4*)&Ws[b][kk][tx * 8 + 4];
            ull bb[4] = {pk2(B01.x, B01.y), pk2(B01.z, B01.w),
                         pk2(B23.x, B23.y), pk2(B23.z, B23.w)};
            float av[8] = {A01.x, A01.y, A01.z, A01.w, A23.x, A23.y, A23.z, A23.w};
#pragma unroll
            for (int i = 0; i < 8; i++) {
                ull ai = pk2(av[i], av[i]);
#pragma unroll
                for (int j = 0; j < 4; j++) acc[i][j] = ffma2(ai, bb[j], acc[i][j]);
            }
        }
        if (kt + 1 < nkt) {
            int nb = b ^ 1;
            float av[8] = {a0.x, a0.y, a0.z, a0.w, a1.x, a1.y, a1.z, a1.w};
            float wv[8] = {w0.x, w0.y, w0.z, w0.w, w1.x, w1.y, w1.z, w1.w};
#pragma unroll
            for (int i = 0; i < 8; i++) { As[nb][aq * 8 + i][ar] = av[i]; Ws[nb][aq * 8 + i][ar] = wv[i]; }
        }
        __syncthreads();
    }

    // epilogue: 8 rows x 8 cols per thread, float4 stores with N guard
#pragma unroll
    for (int i = 0; i < 8; i++) {
        int r = row0 + ty * 8 + i;
        float vals[8];
#pragma unroll
        for (int j = 0; j < 4; j++) {
            float2 v = upk(acc[i][j]);
            vals[j * 2] = v.x; vals[j * 2 + 1] = v.y;
        }
#pragma unroll
        for (int g = 0; g < 2; g++) {
            int c = col0 + tx * 8 + g * 4;
            if (c + 3 < N) {
                float4 o;
                float t4[4];
#pragma unroll
                for (int j = 0; j < 4; j++) {
                    float v = vals[g * 4 + j];
                    if (bias) v += bias[c + j];
                    if (act == 1) v = fmaxf(v, 0.f);
                    else if (act == 2) v = tanhf(v);
                    t4[j] = v;
                }
                if (residual) {
                    float4 old = *(float4*)&C[(size_t)r * N + c];
                    t4[0] += old.x; t4[1] += old.y; t4[2] += old.z; t4[3] += old.w;
                }
                o.x = t4[0]; o.y = t4[1]; o.z = t4[2]; o.w = t4[3];
                *(float4*)&C[(size_t)r * N + c] = o;
            }
        }
    }
}

// ------------------------- layernorm --------------------------------------
__global__ void layernorm_k(const float* __restrict__ in, const float* __restrict__ w,
                            const float* __restrict__ b, float* __restrict__ out)
{
    __shared__ float sbuf[8];
    int t = blockIdx.x, tid = threadIdx.x; // 256 threads
    float2 v = ((const float2*)(in + (size_t)t * DM))[tid];
    float s  = v.x + v.y;
    float sq = v.x * v.x + v.y * v.y;
    float sum  = blk_sum(s, sbuf);
    float sumq = blk_sum(sq, sbuf);
    float mu  = sum * (1.f / DM);
    float var = sumq * (1.f / DM) - mu * mu;
    float rstd = rsqrtf(var + EPSV);
    float2 wv = ((const float2*)w)[tid];
    float2 bv = ((const float2*)b)[tid];
    float2 o;
    o.x = (v.x - mu) * rstd * wv.x + bv.x;
    o.y = (v.y - mu) * rstd * wv.y + bv.y;
    ((float2*)(out + (size_t)t * DM))[tid] = o;
}

// ------------------------- causal dwconv (K=4) + silu ----------------------
__global__ void conv_silu(const float* __restrict__ cw, const float* __restrict__ cb)
{
    int c = blockIdx.x * blockDim.x + threadIdx.x; // < 2560
    int t = blockIdx.y;
    float v = cb[c];
#pragma unroll
    for (int k = 0; k < 4; k++) {
        int tt = t + k - 3;
        if (tt >= 0) v = fmaf(g_zx[(size_t)tt * DPROJ + DIN + c], cw[c * 4 + k], v);
    }
    g_xbc[(size_t)t * CONVD + c] = siluf(v);
}

// ------------------------- dt = softplus(...) ------------------------------
__global__ void dt_kernel(const float* __restrict__ dtb)
{
    int idx = blockIdx.x * blockDim.x + threadIdx.x; // < L*NH
    int t = idx >> 5, h = idx & 31;
    float u = g_zx[(size_t)t * DPROJ + (DPROJ - NH) + h] + dtb[h];
    g_dt[idx] = (u > 20.f) ? u : log1pf(expf(u));
}

// ===========================================================================
// Chunked sequential SSD scan. CTA (h, g4): headdim 64 x states [g4*64,+64).
// thread: p = tid>>2, q = tid&3 owns states [16q,16q+16) as 8 f32x2 pairs.
// SMEM pair layout per step: slot(m) = (m&7)*4 + (m>>3)  -> compute LDS.64 at
// [t*32 + j*4 + q] hits 8 consecutive words per warp: conflict-free.
// Double-buffered chunks of TC=16 steps; 1 sync per chunk.
// ===========================================================================
__global__ void __launch_bounds__(256, 1)
scan_kernel(const float* __restrict__ A_log, const float* __restrict__ Dv)
{
    __shared__ ull   sB[2][TC * 32];
    __shared__ ull   sC[2][TC * 32];
    __shared__ float sX[2][TC * 64];
    __shared__ float sdt[2][TC];
    __shared__ float sdec[2][TC];

    int bx = blockIdx.x;
    int h = bx >> 2, g4 = bx & 3;
    int tid = threadIdx.x;
    int p = tid >> 2, q = tid & 3;
    float A  = -expf(A_log[h]);
    float Dh = Dv[h];
    int base = g4 * 64;

    int lt = tid >> 4;        // loader row 0..15
    int lj = tid & 15;        // loader float4 idx 0..15
    size_t lrow_off = (size_t)lt * CONVD;
    const float* pB = g_xbc + lrow_off + DIN + base + lj * 4;
    const float* pC = pB + DSTATE;
    const float* pX = g_xbc + lrow_off + h * HD + lj * 4;
    size_t cstride = (size_t)TC * CONVD;

    // pair-slot targets for loader's two pairs (m0 = lj*2, m1 = lj*2+1)
    int m0 = lj * 2, m1 = lj * 2 + 1;
    int s0 = (m0 & 7) * 4 + (m0 >> 3);
    int s1 = (m1 & 7) * 4 + (m1 >> 3);

    ull st[8];
#pragma unroll
    for (int i = 0; i < 8; i++) st[i] = 0ull;

    // ---- load chunk 0 into buf 0
    {
        float4 vB = *(const float4*)pB;
        float4 vC = *(const float4*)pC;
        float4 vX = *(const float4*)pX;
        sB[0][lt * 32 + s0] = pk2(vB.x, vB.y);
        sB[0][lt * 32 + s1] = pk2(vB.z, vB.w);
        sC[0][lt * 32 + s0] = pk2(vC.x, vC.y);
        sC[0][lt * 32 + s1] = pk2(vC.z, vC.w);
        *(float4*)&sX[0][lt * 64 + lj * 4] = vX;
        if (tid < TC) {
            float d = g_dt[tid * NH + h];
            sdt[0][tid] = d;
            sdec[0][tid] = __expf(d * A);
        }
    }
    __syncthreads();

    float* outp = &g_yp[g4][(size_t)h * HD + p];

    for (int c = 0; c < NC; c++) {
        int b = c & 1;
        float4 vB, vC, vX; float rd = 0.f;
        if (c + 1 < NC) {
            size_t off = (size_t)(c + 1) * cstride;
            vB = *(const float4*)(pB + off);
            vC = *(const float4*)(pC + off);
            vX = *(const float4*)(pX + off);
            if (tid < TC) rd = g_dt[((c + 1) * TC + tid) * NH + h];
        }

        // ---- compute TC steps from buf b
#pragma unroll 4
        for (int t = 0; t < TC; t++) {
            float dt_t = sdt[b][t];
            float dec  = sdec[b][t];
            float xp   = sX[b][t * 64 + p];
            float xs   = dt_t * xp;
            ull xs2  = pk2(xs, xs);
            ull dec2 = pk2(dec, dec);
            ull acc2 = 0ull;
            const ull* rB = &sB[b][t * 32 + q];
            const ull* rC = &sC[b][t * 32 + q];
#pragma unroll
            for (int j = 0; j < 8; j++) {
                ull b2 = rB[j * 4];
                ull c2 = rC[j * 4];
                st[j] = ffma2(xs2, b2, fmul2(st[j], dec2));
                acc2  = ffma2(st[j], c2, acc2);
            }
            float2 af = upk(acc2);
            float acc = af.x + af.y;
            acc += __shfl_xor_sync(0xffffffffu, acc, 1);
            acc += __shfl_xor_sync(0xffffffffu, acc, 2);
            if (q == 0) {
                float outv = acc;
                if (g4 == 0) outv = fmaf(Dh, xp, outv);
                outp[(size_t)(c * TC + t) * DIN] = outv;
            }
        }

        if (c + 1 < NC) {
            int nb = b ^ 1;
            sB[nb][lt * 32 + s0] = pk2(vB.x, vB.y);
            sB[nb][lt * 32 + s1] = pk2(vB.z, vB.w);
            sC[nb][lt * 32 + s0] = pk2(vC.x, vC.y);
            sC[nb][lt * 32 + s1] = pk2(vC.z, vC.w);
            *(float4*)&sX[nb][lt * 64 + lj * 4] = vX;
            if (tid < TC) {
                sdt[nb][tid] = rd;
                sdec[nb][tid] = __expf(rd * A);
            }
        }
        __syncthreads();
    }
}

// ------------------------- gate + rmsnorm ----------------------------------
__global__ void gate_rms(const float* __restrict__ rmsw)
{
    __shared__ float sbuf[8];
    int t = blockIdx.x, tid = threadIdx.x; // 256 threads
    float ry[8];
    float ss = 0.f;
#pragma unroll
    for (int i = 0; i < 8; i++) {
        int e = tid + i * 256;
        size_t idx = (size_t)t * DIN + e;
        float z  = g_zx[(size_t)t * DPROJ + e];
        float yv = (g_yp[0][idx] + g_yp[1][idx] + g_yp[2][idx] + g_yp[3][idx]) * siluf(z);
        ry[i] = yv;
        ss += yv * yv;
    }
    float tot = blk_sum(ss, sbuf);
    float scale = rsqrtf(tot * (1.f / DIN) + EPSV);
#pragma unroll
    for (int i = 0; i < 8; i++) {
        int e = tid + i * 256;
        g_yn[(size_t)t * DIN + e] = ry[i] * scale * rmsw[e];
    }
}

// ------------------------- attention logit per row -------------------------
__global__ void alog_kernel(const float* __restrict__ w2, const float* __restrict__ b2)
{
    int warp = threadIdx.x >> 5, lane = threadIdx.x & 31;
    int row = blockIdx.x * 8 + warp;
    float s = 0.f;
#pragma unroll
    for (int i = 0; i < 4; i++)
        s = fmaf(g_s1[(size_t)row * 128 + lane + i * 32], w2[lane + i * 32], s);
#pragma unroll
    for (int o = 16; o; o >>= 1) s += __shfl_xor_sync(0xffffffffu, s, o);
    if (lane == 0) g_alog[row] = s + b2[0];
}

// ------------------------- softmax over L ----------------------------------
__global__ void softmax_l()
{
    __shared__ float sbuf[32];
    int tid = threadIdx.x; // 1024
    float v[4], e[4];
    float mx = -INFINITY;
#pragma unroll
    for (int i = 0; i < 4; i++) { v[i] = g_alog[tid + i * 1024]; mx = fmaxf(mx, v[i]); }
    mx = blk_max(mx, sbuf);
    float s = 0.f;
#pragma unroll
    for (int i = 0; i < 4; i++) { e[i] = expf(v[i] - mx); s += e[i]; }
    s = blk_sum(s, sbuf);
    float inv = 1.f / s;
#pragma unroll
    for (int i = 0; i < 4; i++) g_att[tid + i * 1024] = e[i] * inv;
}

// ------------------------- pooled partials ---------------------------------
__global__ void pooled_part()
{
    int b = blockIdx.x, tid = threadIdx.x; // 512 threads
    float acc = 0.f;
    for (int tt = 0; tt < 128; tt++) {
        int t = b * 128 + tt;
        acc = fmaf(g_att[t], g_hn[(size_t)t * DM + tid], acc);
    }
    g_part[b * DM + tid] = acc;
}

// ------------------------- final -------------------------------------------
__global__ void finalize_kernel(const float* __restrict__ cls_w, const float* __restrict__ cls_b,
                                float* __restrict__ out, int out_size)
{
    __shared__ float spool[DM];
    __shared__ float slog[4];
    int tid = threadIdx.x; // 512
    float acc = 0.f;
#pragma unroll
    for (int b = 0; b < 32; b++) acc += g_part[b * DM + tid];
    spool[tid] = acc;
    __syncthreads();
    int w = tid >> 5, lane = tid & 31;
    if (w < 4) {
        float s = 0.f;
#pragma unroll
        for (int i = 0; i < 16; i++)
            s = fmaf(spool[lane + i * 32], cls_w[w * DM + lane + i * 32], s);
#pragma unroll
        for (int o = 16; o; o >>= 1) s += __shfl_xor_sync(0xffffffffu, s, o);
        if (lane == 0) slog[w] = s + cls_b[w];
    }
    __syncthreads();
    if (tid == 0) {
        float l[4] = {slog[0], slog[1], slog[2], slog[3]};
        float mx = fmaxf(fmaxf(l[0], l[1]), fmaxf(l[2], l[3]));
        float e[4], s = 0.f;
#pragma unroll
        for (int c = 0; c < 4; c++) { e[c] = expf(l[c] - mx); s += e[c]; }
        int am = 0;
#pragma unroll
        for (int c = 1; c < 4; c++) if (l[c] > l[am]) am = c;
        if (out_size >= 4) { out[0] = l[0]; out[1] = l[1]; out[2] = l[2]; out[3] = l[3]; }
        if (out_size >= 8) { for (int c = 0; c < 4; c++) out[4 + c] = e[c] / s; }
        if (out_size >= 9) out[8] = (float)am;
    }
}

// ===========================================================================
extern "C" void kernel_launch(void* const* d_in, const int* in_sizes, int n_in,
                              void* d_out, int out_size)
{
    const float* x        = (const float*)d_in[0];
    const float* fc1_w    = (const float*)d_in[1];
    const float* fc1_b    = (const float*)d_in[2];
    const float* ln_w     = (const float*)d_in[3];
    const float* ln_b     = (const float*)d_in[4];
    const float* in_proj  = (const float*)d_in[5];
    const float* conv_w   = (const float*)d_in[6];
    const float* conv_b   = (const float*)d_in[7];
    const float* dt_bias  = (const float*)d_in[8];
    const float* A_log    = (const float*)d_in[9];
    const float* Dvec     = (const float*)d_in[10];
    const float* rms_w    = (const float*)d_in[11];
    const float* out_proj = (const float*)d_in[12];
    const float* norm_w   = (const float*)d_in[13];
    const float* norm_b   = (const float*)d_in[14];
    const float* att_w1   = (const float*)d_in[15];
    const float* att_b1   = (const float*)d_in[16];
    const float* att_w2   = (const float*)d_in[17];
    const float* att_b2   = (const float*)d_in[18];
    const float* cls_w    = (const float*)d_in[19];
    const float* cls_b    = (const float*)d_in[20];
    float* out = (float*)d_out;

    float *h, *hn, *zx, *yn, *s1;
    cudaGetSymbolAddress((void**)&h,  g_h);
    cudaGetSymbolAddress((void**)&hn, g_hn);
    cudaGetSymbolAddress((void**)&zx, g_zx);
    cudaGetSymbolAddress((void**)&yn, g_yn);
    cudaGetSymbolAddress((void**)&s1, g_s1);

    // h = relu(x @ fc1_w^T + fc1_b)
    gemm_nt<<<dim3(DM / 128, L / 128), 256>>>(x, fc1_w, fc1_b, h, DM, INDIM, 1, 0);

    for (int layer = 0; layer < 2; layer++) {
        layernorm_k<<<L, 256>>>(h, ln_w + layer * DM, ln_b + layer * DM, hn);
        gemm_nt<<<dim3((DPROJ + 127) / 128, L / 128), 256>>>(
            hn, in_proj + (size_t)layer * DPROJ * DM, nullptr, zx, DPROJ, DM, 0, 0);
        conv_silu<<<dim3(CONVD / 256, L), 256>>>(conv_w + layer * CONVD * 4,
                                                 conv_b + layer * CONVD);
        dt_kernel<<<(L * NH) / 256, 256>>>(dt_bias + layer * NH);
        scan_kernel<<<NH * SPLIT, 256>>>(A_log + layer * NH, Dvec + layer * NH);
        gate_rms<<<L, 256>>>(rms_w + layer * DIN);
        gemm_nt<<<dim3(DM / 128, L / 128), 256>>>(
            yn, out_proj + (size_t)layer * DM * DIN, nullptr, h, DM, DIN, 0, 1);
    }

    layernorm_k<<<L, 256>>>(h, norm_w, norm_b, hn);
    gemm_nt<<<dim3(1, L / 128), 256>>>(hn, att_w1, att_b1, s1, 128, DM, 2, 0);
    alog_kernel<<<L / 8, 256>>>(att_w2, att_b2);
    softmax_l<<<1, 1024>>>();
    pooled_part<<<32, 512>>>();
    finalize_kernel<<<1, 512>>>(cls_w, cls_b, out, out_size);
}

// round 9
// speedup vs baseline: 2.9673x; 1.2236x over previous
#include <cuda_runtime.h>
#include <cuda_bf16.h>
#include <math.h>
#include <stdint.h>

#define L       4096
#define INDIM   1024
#define DM      512
#define DIN     2048
#define DSTATE  256
#define CONVD   2560
#define DPROJ   4640
#define NH      32
#define HD      64
#define EPSV    1e-5f
#define SPLIT   4
#define TC      16          // scan chunk length
#define NC      (L / TC)

typedef unsigned long long ull;

// ------------------------- packed f32x2 helpers (scan) ---------------------
__device__ __forceinline__ ull pk2(float x, float y) {
    ull r; asm("mov.b64 %0,{%1,%2};" : "=l"(r) : "f"(x), "f"(y)); return r;
}
__device__ __forceinline__ float2 upk(ull v) {
    float2 f; asm("mov.b64 {%0,%1},%2;" : "=f"(f.x), "=f"(f.y) : "l"(v)); return f;
}
__device__ __forceinline__ ull ffma2(ull a, ull b, ull c) {
    ull r; asm("fma.rn.f32x2 %0,%1,%2,%3;" : "=l"(r) : "l"(a), "l"(b), "l"(c)); return r;
}
__device__ __forceinline__ ull fmul2(ull a, ull b) {
    ull r; asm("mul.rn.f32x2 %0,%1,%2;" : "=l"(r) : "l"(a), "l"(b)); return r;
}
__device__ __forceinline__ uint32_t s2u(const void* p) {
    uint32_t a;
    asm("{ .reg .u64 t; cvta.to.shared.u64 t, %1; cvt.u32.u64 %0, t; }" : "=r"(a) : "l"(p));
    return a;
}

// ------------------------- scratch ----------------------------------------
__device__ __align__(256) float g_h  [L * DM];
__device__ __align__(256) float g_hn [L * DM];
__device__ __align__(256) float g_zx [(size_t)L * DPROJ];
__device__ __align__(256) float g_xbc[(size_t)L * CONVD];
__device__ __align__(256) float g_dt [L * NH];
__device__ __align__(256) float g_yp [SPLIT][(size_t)L * DIN];
__device__ __align__(256) float g_yn [(size_t)L * DIN];
__device__ __align__(256) float g_s1 [L * 128];
__device__ __align__(256) float g_alog[L];
__device__ __align__(256) float g_att [L];
__device__ __align__(256) float g_part[32 * DM];
__device__ __align__(256) __nv_bfloat16 g_a2[(size_t)4096 * 6144];  // [M, 3K] max
__device__ __align__(256) __nv_bfloat16 g_w2[(size_t)4736 * 1536];  // [Npad, 3K] max

// ------------------------- reductions -------------------------------------
__device__ __forceinline__ float blk_sum(float v, float* sbuf) {
    int lane = threadIdx.x & 31, w = threadIdx.x >> 5;
    int nw = blockDim.x >> 5;
#pragma unroll
    for (int o = 16; o; o >>= 1) v += __shfl_xor_sync(0xffffffffu, v, o);
    if (lane == 0) sbuf[w] = v;
    __syncthreads();
    float r = (threadIdx.x < nw) ? sbuf[threadIdx.x] : 0.f;
    if (w == 0) {
#pragma unroll
        for (int o = 16; o; o >>= 1) r += __shfl_xor_sync(0xffffffffu, r, o);
        if (lane == 0) sbuf[0] = r;
    }
    __syncthreads();
    float out = sbuf[0];
    __syncthreads();
    return out;
}

__device__ __forceinline__ float blk_max(float v, float* sbuf) {
    int lane = threadIdx.x & 31, w = threadIdx.x >> 5;
    int nw = blockDim.x >> 5;
#pragma unroll
    for (int o = 16; o; o >>= 1) v = fmaxf(v, __shfl_xor_sync(0xffffffffu, v, o));
    if (lane == 0) sbuf[w] = v;
    __syncthreads();
    float r = (threadIdx.x < nw) ? sbuf[threadIdx.x] : -INFINITY;
    if (w == 0) {
#pragma unroll
        for (int o = 16; o; o >>= 1) r = fmaxf(r, __shfl_xor_sync(0xffffffffu, r, o));
        if (lane == 0) sbuf[0] = r;
    }
    __syncthreads();
    float out = sbuf[0];
    __syncthreads();
    return out;
}

__device__ __forceinline__ float siluf(float x) { return x / (1.f + __expf(-x)); }

// ===========================================================================
// fp32 -> bf16 hi/lo split, K-extended layouts:
//   A2[r] = [ hi | lo | hi ],  W2[r] = [ hi | hi | lo ]  (rows >= Nrows zeroed)
// => A2 . W2 over K'=3K = Ah*Wh + Al*Wh + Ah*Wl (~fp32-accurate)
// ===========================================================================
__global__ void cvt_a_k(const float* __restrict__ A, __nv_bfloat16* __restrict__ A2,
                        int kshift, size_t total)
{
    size_t idx = (size_t)blockIdx.x * blockDim.x + threadIdx.x;
    if (idx >= total) return;
    int K = 1 << kshift;
    size_t r = idx >> kshift;
    int k = (int)(idx & (K - 1));
    float x = A[idx];
    __nv_bfloat16 hi = __float2bfloat16(x);
    __nv_bfloat16 lo = __float2bfloat16(x - __bfloat162float(hi));
    size_t ro = r * (size_t)(3 * K);
    A2[ro + k] = hi;
    A2[ro + K + k] = lo;
    A2[ro + 2 * K + k] = hi;
}

__global__ void cvt_w_k(const float* __restrict__ W, __nv_bfloat16* __restrict__ W2,
                        int Nrows, int kshift, size_t total)
{
    size_t idx = (size_t)blockIdx.x * blockDim.x + threadIdx.x;
    if (idx >= total) return;
    int K = 1 << kshift;
    size_t r = idx >> kshift;
    int k = (int)(idx & (K - 1));
    __nv_bfloat16 hi, lo;
    if ((int)r < Nrows) {
        float x = W[r * (size_t)K + k];
        hi = __float2bfloat16(x);
        lo = __float2bfloat16(x - __bfloat162float(hi));
    } else {
        hi = __float2bfloat16(0.f);
        lo = hi;
    }
    size_t ro = r * (size_t)(3 * K);
    W2[ro + k] = hi;
    W2[ro + K + k] = hi;
    W2[ro + 2 * K + k] = lo;
}

// ===========================================================================
// bf16 mma.sync GEMM: C[M,N] = act(A2[M,Kp] . W2[Npad,Kp]^T + bias) (+C)
// 128x128x64 CTA tile, 256 thr (8 warps 2x4, warp tile 64x32),
// mma.sync.m16n8k16.row.col.f32.bf16.bf16.f32, SW128-swizzled SMEM,
// ldmatrix.x4 frags, double-buffered with register prefetch, 1 sync/tile.
// Swizzle: addr = row*128 + ((chunk + ks*32) ^ ((row&7)<<4)); the XOR covers
// the FULL within-row offset (chunk + ks*32 <= 112 < 128 -> never overflows).
// Kp%64==0, M%128==0, grid.x = Npad/128 (W2 rows padded).
// ===========================================================================
#define GM_A0 0
#define GM_W0 16384
#define GM_A1 32768
#define GM_W1 49152
#define GM_SMEM 65536

#define LDSM4(r0, r1, r2, r3, addr) \
    asm volatile("ldmatrix.sync.aligned.m8n8.x4.shared.b16 {%0,%1,%2,%3}, [%4];" \
        : "=r"(r0), "=r"(r1), "=r"(r2), "=r"(r3) : "r"(addr))

#define MMA16816(d, a, b) \
    asm volatile("mma.sync.aligned.m16n8k16.row.col.f32.bf16.bf16.f32 " \
        "{%0,%1,%2,%3}, {%4,%5,%6,%7}, {%8,%9}, {%0,%1,%2,%3};" \
        : "+f"((d)[0]), "+f"((d)[1]), "+f"((d)[2]), "+f"((d)[3]) \
        : "r"((a)[0]), "r"((a)[1]), "r"((a)[2]), "r"((a)[3]), "r"((b)[0]), "r"((b)[1]))

__global__ __launch_bounds__(256, 1)
void gemm_mma(const __nv_bfloat16* __restrict__ A2, const __nv_bfloat16* __restrict__ W2,
              const float* __restrict__ bias, float* __restrict__ C,
              int N, int Kp, int act, int residual)
{
    extern __shared__ __align__(1024) char smem[];
    uint32_t sb = s2u(smem);
    int tid = threadIdx.x, wid = tid >> 5, lane = tid & 31;
    int row0 = blockIdx.y * 128, col0 = blockIdx.x * 128;
    int warp_m = (wid >> 2) * 64, warp_n = (wid & 3) * 32;

    float acc[4][4][4];
#pragma unroll
    for (int i = 0; i < 4; i++)
#pragma unroll
        for (int j = 0; j < 4; j++)
#pragma unroll
            for (int f = 0; f < 4; f++) acc[i][j][f] = 0.f;

    // ---- loader mapping: thread -> row (tid>>1), 32 elems (4x16B) per matrix
    int lrow = tid >> 1, bch = (tid & 1) * 4;
    const __nv_bfloat16* pa = A2 + (size_t)(row0 + lrow) * Kp + bch * 8;
    const __nv_bfloat16* pw = W2 + (size_t)(col0 + lrow) * Kp + bch * 8;
    uint32_t soff[4];
#pragma unroll
    for (int i = 0; i < 4; i++)
        soff[i] = lrow * 128 + ((((bch + i) * 16) ^ ((lrow & 7) << 4)));

    // ---- compute-side ldmatrix address components (row base + chunk + sx)
    uint32_t aBase[4], aSx[4];
    uint32_t aCh = ((uint32_t)lane >> 4) * 16;   // A chunk constant (0 or 16)
#pragma unroll
    for (int mt = 0; mt < 4; mt++) {
        int ar = warp_m + mt * 16 + (lane & 15);
        aBase[mt] = ar * 128;
        aSx[mt] = (ar & 7) << 4;
    }
    uint32_t bBase[2], bSx[2], bCh;
    {
        int j = lane >> 3, t = lane & 7;
        bCh = (j & 1) * 16;                      // B chunk constant (0 or 16)
#pragma unroll
        for (int nt2 = 0; nt2 < 2; nt2++) {
            int br = warp_n + nt2 * 16 + ((j >> 1) << 3) + t;
            bBase[nt2] = br * 128;
            bSx[nt2] = (br & 7) << 4;
        }
    }

    int nkt = Kp >> 6;

    // ---- load tile 0 into buffer 0
    uint4 ra[4], rw[4];
#pragma unroll
    for (int i = 0; i < 4; i++) {
        ra[i] = *(const uint4*)(pa + i * 8);
        rw[i] = *(const uint4*)(pw + i * 8);
    }
#pragma unroll
    for (int i = 0; i < 4; i++) {
        *(uint4*)(smem + GM_A0 + soff[i]) = ra[i];
        *(uint4*)(smem + GM_W0 + soff[i]) = rw[i];
    }
    __syncthreads();

    for (int kt = 0; kt < nkt; kt++) {
        int b = kt & 1;
        uint32_t abuf = sb + (b ? GM_A1 : GM_A0);
        uint32_t wbuf = sb + (b ? GM_W1 : GM_W0);
        if (kt + 1 < nkt) {
#pragma unroll
            for (int i = 0; i < 4; i++) {
                ra[i] = *(const uint4*)(pa + (kt + 1) * 64 + i * 8);
                rw[i] = *(const uint4*)(pw + (kt + 1) * 64 + i * 8);
            }
        }
#pragma unroll
        for (int ks = 0; ks < 4; ks++) {
            uint32_t af[4][4], bf[4][2];
#pragma unroll
            for (int mt = 0; mt < 4; mt++)
                LDSM4(af[mt][0], af[mt][1], af[mt][2], af[mt][3],
                      abuf + aBase[mt] + ((aCh + ks * 32) ^ aSx[mt]));
#pragma unroll
            for (int nt2 = 0; nt2 < 2; nt2++) {
                uint32_t r0, r1, r2, r3;
                LDSM4(r0, r1, r2, r3,
                      wbuf + bBase[nt2] + ((bCh + ks * 32) ^ bSx[nt2]));
                bf[nt2 * 2][0] = r0; bf[nt2 * 2][1] = r1;
                bf[nt2 * 2 + 1][0] = r2; bf[nt2 * 2 + 1][1] = r3;
            }
#pragma unroll
            for (int mt = 0; mt < 4; mt++)
#pragma unroll
                for (int nt = 0; nt < 4; nt++)
                    MMA16816(acc[mt][nt], af[mt], bf[nt]);
        }
        if (kt + 1 < nkt) {
            char* ab = smem + (b ? GM_A0 : GM_A1);
            char* wb = smem + (b ? GM_W0 : GM_W1);
#pragma unroll
            for (int i = 0; i < 4; i++) {
                *(uint4*)(ab + soff[i]) = ra[i];
                *(uint4*)(wb + soff[i]) = rw[i];
            }
        }
        __syncthreads();
    }

    // ---- epilogue: frag (d0,d1)->row r, cols cc,cc+1 ; (d2,d3)->row r+8
#pragma unroll
    for (int mt = 0; mt < 4; mt++) {
        int rbase = row0 + warp_m + mt * 16 + (lane >> 2);
#pragma unroll
        for (int nt = 0; nt < 4; nt++) {
            int cc = col0 + warp_n + nt * 8 + (lane & 3) * 2;
            if (cc < N) {
#pragma unroll
                for (int half = 0; half < 2; half++) {
                    int r = rbase + half * 8;
                    float v0 = acc[mt][nt][half * 2];
                    float v1 = acc[mt][nt][half * 2 + 1];
                    if (bias) { v0 += bias[cc]; v1 += bias[cc + 1]; }
                    if (act == 1) { v0 = fmaxf(v0, 0.f); v1 = fmaxf(v1, 0.f); }
                    else if (act == 2) { v0 = tanhf(v0); v1 = tanhf(v1); }
                    float2* dst = (float2*)&C[(size_t)r * N + cc];
                    if (residual) {
                        float2 o = *dst;
                        v0 += o.x; v1 += o.y;
                    }
                    *dst = make_float2(v0, v1);
                }
            }
        }
    }
}

// ------------------------- layernorm --------------------------------------
__global__ void layernorm_k(const float* __restrict__ in, const float* __restrict__ w,
                            const float* __restrict__ b, float* __restrict__ out)
{
    __shared__ float sbuf[8];
    int t = blockIdx.x, tid = threadIdx.x; // 256 threads
    float2 v = ((const float2*)(in + (size_t)t * DM))[tid];
    float s  = v.x + v.y;
    float sq = v.x * v.x + v.y * v.y;
    float sum  = blk_sum(s, sbuf);
    float sumq = blk_sum(sq, sbuf);
    float mu  = sum * (1.f / DM);
    float var = sumq * (1.f / DM) - mu * mu;
    float rstd = rsqrtf(var + EPSV);
    float2 wv = ((const float2*)w)[tid];
    float2 bv = ((const float2*)b)[tid];
    float2 o;
    o.x = (v.x - mu) * rstd * wv.x + bv.x;
    o.y = (v.y - mu) * rstd * wv.y + bv.y;
    ((float2*)(out + (size_t)t * DM))[tid] = o;
}

// ------------------------- causal dwconv (K=4) + silu ----------------------
__global__ void conv_silu(const float* __restrict__ cw, const float* __restrict__ cb)
{
    int c = blockIdx.x * blockDim.x + threadIdx.x; // < 2560
    int t = blockIdx.y;
    float v = cb[c];
#pragma unroll
    for (int k = 0; k < 4; k++) {
        int tt = t + k - 3;
        if (tt >= 0) v = fmaf(g_zx[(size_t)tt * DPROJ + DIN + c], cw[c * 4 + k], v);
    }
    g_xbc[(size_t)t * CONVD + c] = siluf(v);
}

// ------------------------- dt = softplus(...) ------------------------------
__global__ void dt_kernel(const float* __restrict__ dtb)
{
    int idx = blockIdx.x * blockDim.x + threadIdx.x; // < L*NH
    int t = idx >> 5, h = idx & 31;
    float u = g_zx[(size_t)t * DPROJ + (DPROJ - NH) + h] + dtb[h];
    g_dt[idx] = (u > 20.f) ? u : log1pf(expf(u));
}

// ===========================================================================
// Chunked sequential SSD scan (unchanged from R4)
// ===========================================================================
__global__ void __launch_bounds__(256, 1)
scan_kernel(const float* __restrict__ A_log, const float* __restrict__ Dv)
{
    __shared__ ull   sB[2][TC * 32];
    __shared__ ull   sC[2][TC * 32];
    __shared__ float sX[2][TC * 64];
    __shared__ float sdt[2][TC];
    __shared__ float sdec[2][TC];

    int bx = blockIdx.x;
    int h = bx >> 2, g4 = bx & 3;
    int tid = threadIdx.x;
    int p = tid >> 2, q = tid & 3;
    float A  = -expf(A_log[h]);
    float Dh = Dv[h];
    int base = g4 * 64;

    int lt = tid >> 4;
    int lj = tid & 15;
    size_t lrow_off = (size_t)lt * CONVD;
    const float* pB = g_xbc + lrow_off + DIN + base + lj * 4;
    const float* pC = pB + DSTATE;
    const float* pX = g_xbc + lrow_off + h * HD + lj * 4;
    size_t cstride = (size_t)TC * CONVD;

    int m0 = lj * 2, m1 = lj * 2 + 1;
    int s0 = (m0 & 7) * 4 + (m0 >> 3);
    int s1 = (m1 & 7) * 4 + (m1 >> 3);

    ull st[8];
#pragma unroll
    for (int i = 0; i < 8; i++) st[i] = 0ull;

    {
        float4 vB = *(const float4*)pB;
        float4 vC = *(const float4*)pC;
        float4 vX = *(const float4*)pX;
        sB[0][lt * 32 + s0] = pk2(vB.x, vB.y);
        sB[0][lt * 32 + s1] = pk2(vB.z, vB.w);
        sC[0][lt * 32 + s0] = pk2(vC.x, vC.y);
        sC[0][lt * 32 + s1] = pk2(vC.z, vC.w);
        *(float4*)&sX[0][lt * 64 + lj * 4] = vX;
        if (tid < TC) {
            float d = g_dt[tid * NH + h];
            sdt[0][tid] = d;
            sdec[0][tid] = __expf(d * A);
        }
    }
    __syncthreads();

    float* outp = &g_yp[g4][(size_t)h * HD + p];

    for (int c = 0; c < NC; c++) {
        int b = c & 1;
        float4 vB, vC, vX; float rd = 0.f;
        if (c + 1 < NC) {
            size_t off = (size_t)(c + 1) * cstride;
            vB = *(const float4*)(pB + off);
            vC = *(const float4*)(pC + off);
            vX = *(const float4*)(pX + off);
            if (tid < TC) rd = g_dt[((c + 1) * TC + tid) * NH + h];
        }

#pragma unroll 4
        for (int t = 0; t < TC; t++) {
            float dt_t = sdt[b][t];
            float dec  = sdec[b][t];
            float xp   = sX[b][t * 64 + p];
            float xs   = dt_t * xp;
            ull xs2  = pk2(xs, xs);
            ull dec2 = pk2(dec, dec);
            ull acc2 = 0ull;
            const ull* rB = &sB[b][t * 32 + q];
            const ull* rC = &sC[b][t * 32 + q];
#pragma unroll
            for (int j = 0; j < 8; j++) {
                ull b2 = rB[j * 4];
                ull c2 = rC[j * 4];
                st[j] = ffma2(xs2, b2, fmul2(st[j], dec2));
                acc2  = ffma2(st[j], c2, acc2);
            }
            float2 af = upk(acc2);
            float acc = af.x + af.y;
            acc += __shfl_xor_sync(0xffffffffu, acc, 1);
            acc += __shfl_xor_sync(0xffffffffu, acc, 2);
            if (q == 0) {
                float outv = acc;
                if (g4 == 0) outv = fmaf(Dh, xp, outv);
                outp[(size_t)(c * TC + t) * DIN] = outv;
            }
        }

        if (c + 1 < NC) {
            int nb = b ^ 1;
            sB[nb][lt * 32 + s0] = pk2(vB.x, vB.y);
            sB[nb][lt * 32 + s1] = pk2(vB.z, vB.w);
            sC[nb][lt * 32 + s0] = pk2(vC.x, vC.y);
            sC[nb][lt * 32 + s1] = pk2(vC.z, vC.w);
            *(float4*)&sX[nb][lt * 64 + lj * 4] = vX;
            if (tid < TC) {
                sdt[nb][tid] = rd;
                sdec[nb][tid] = __expf(rd * A);
            }
        }
        __syncthreads();
    }
}

// ------------------------- gate + rmsnorm ----------------------------------
__global__ void gate_rms(const float* __restrict__ rmsw)
{
    __shared__ float sbuf[8];
    int t = blockIdx.x, tid = threadIdx.x; // 256 threads
    float ry[8];
    float ss = 0.f;
#pragma unroll
    for (int i = 0; i < 8; i++) {
        int e = tid + i * 256;
        size_t idx = (size_t)t * DIN + e;
        float z  = g_zx[(size_t)t * DPROJ + e];
        float yv = (g_yp[0][idx] + g_yp[1][idx] + g_yp[2][idx] + g_yp[3][idx]) * siluf(z);
        ry[i] = yv;
        ss += yv * yv;
    }
    float tot = blk_sum(ss, sbuf);
    float scale = rsqrtf(tot * (1.f / DIN) + EPSV);
#pragma unroll
    for (int i = 0; i < 8; i++) {
        int e = tid + i * 256;
        g_yn[(size_t)t * DIN + e] = ry[i] * scale * rmsw[e];
    }
}

// ------------------------- attention logit per row -------------------------
__global__ void alog_kernel(const float* __restrict__ w2, const float* __restrict__ b2)
{
    int warp = threadIdx.x >> 5, lane = threadIdx.x & 31;
    int row = blockIdx.x * 8 + warp;
    float s = 0.f;
#pragma unroll
    for (int i = 0; i < 4; i++)
        s = fmaf(g_s1[(size_t)row * 128 + lane + i * 32], w2[lane + i * 32], s);
#pragma unroll
    for (int o = 16; o; o >>= 1) s += __shfl_xor_sync(0xffffffffu, s, o);
    if (lane == 0) g_alog[row] = s + b2[0];
}

// ------------------------- softmax over L ----------------------------------
__global__ void softmax_l()
{
    __shared__ float sbuf[32];
    int tid = threadIdx.x; // 1024
    float v[4], e[4];
    float mx = -INFINITY;
#pragma unroll
    for (int i = 0; i < 4; i++) { v[i] = g_alog[tid + i * 1024]; mx = fmaxf(mx, v[i]); }
    mx = blk_max(mx, sbuf);
    float s = 0.f;
#pragma unroll
    for (int i = 0; i < 4; i++) { e[i] = expf(v[i] - mx); s += e[i]; }
    s = blk_sum(s, sbuf);
    float inv = 1.f / s;
#pragma unroll
    for (int i = 0; i < 4; i++) g_att[tid + i * 1024] = e[i] * inv;
}

// ------------------------- pooled partials ---------------------------------
__global__ void pooled_part()
{
    int b = blockIdx.x, tid = threadIdx.x; // 512 threads
    float acc = 0.f;
    for (int tt = 0; tt < 128; tt++) {
        int t = b * 128 + tt;
        acc = fmaf(g_att[t], g_hn[(size_t)t * DM + tid], acc);
    }
    g_part[b * DM + tid] = acc;
}

// ------------------------- final -------------------------------------------
__global__ void finalize_kernel(const float* __restrict__ cls_w, const float* __restrict__ cls_b,
                                float* __restrict__ out, int out_size)
{
    __shared__ float spool[DM];
    __shared__ float slog[4];
    int tid = threadIdx.x; // 512
    float acc = 0.f;
#pragma unroll
    for (int b = 0; b < 32; b++) acc += g_part[b * DM + tid];
    spool[tid] = acc;
    __syncthreads();
    int w = tid >> 5, lane = tid & 31;
    if (w < 4) {
        float s = 0.f;
#pragma unroll
        for (int i = 0; i < 16; i++)
            s = fmaf(spool[lane + i * 32], cls_w[w * DM + lane + i * 32], s);
#pragma unroll
        for (int o = 16; o; o >>= 1) s += __shfl_xor_sync(0xffffffffu, s, o);
        if (lane == 0) slog[w] = s + cls_b[w];
    }
    __syncthreads();
    if (tid == 0) {
        float l[4] = {slog[0], slog[1], slog[2], slog[3]};
        float mx = fmaxf(fmaxf(l[0], l[1]), fmaxf(l[2], l[3]));
        float e[4], s = 0.f;
#pragma unroll
        for (int c = 0; c < 4; c++) { e[c] = expf(l[c] - mx); s += e[c]; }
        int am = 0;
#pragma unroll
        for (int c = 1; c < 4; c++) if (l[c] > l[am]) am = c;
        if (out_size >= 4) { out[0] = l[0]; out[1] = l[1]; out[2] = l[2]; out[3] = l[3]; }
        if (out_size >= 8) { for (int c = 0; c < 4; c++) out[4 + c] = e[c] / s; }
        if (out_size >= 9) out[8] = (float)am;
    }
}

// ===========================================================================
extern "C" void kernel_launch(void* const* d_in, const int* in_sizes, int n_in,
                              void* d_out, int out_size)
{
    const float* x        = (const float*)d_in[0];
    const float* fc1_w    = (const float*)d_in[1];
    const float* fc1_b    = (const float*)d_in[2];
    const float* ln_w     = (const float*)d_in[3];
    const float* ln_b     = (const float*)d_in[4];
    const float* in_proj  = (const float*)d_in[5];
    const float* conv_w   = (const float*)d_in[6];
    const float* conv_b   = (const float*)d_in[7];
    const float* dt_bias  = (const float*)d_in[8];
    const float* A_log    = (const float*)d_in[9];
    const float* Dvec     = (const float*)d_in[10];
    const float* rms_w    = (const float*)d_in[11];
    const float* out_proj = (const float*)d_in[12];
    const float* norm_w   = (const float*)d_in[13];
    const float* norm_b   = (const float*)d_in[14];
    const float* att_w1   = (const float*)d_in[15];
    const float* att_b1   = (const float*)d_in[16];
    const float* att_w2   = (const float*)d_in[17];
    const float* att_b2   = (const float*)d_in[18];
    const float* cls_w    = (const float*)d_in[19];
    const float* cls_b    = (const float*)d_in[20];
    float* out = (float*)d_out;

    float *h, *hn, *zx, *yn, *s1;
    __nv_bfloat16 *a2, *w2;
    cudaGetSymbolAddress((void**)&h,  g_h);
    cudaGetSymbolAddress((void**)&hn, g_hn);
    cudaGetSymbolAddress((void**)&zx, g_zx);
    cudaGetSymbolAddress((void**)&yn, g_yn);
    cudaGetSymbolAddress((void**)&s1, g_s1);
    cudaGetSymbolAddress((void**)&a2, g_a2);
    cudaGetSymbolAddress((void**)&w2, g_w2);

    cudaFuncSetAttribute(gemm_mma, cudaFuncAttributeMaxDynamicSharedMemorySize, GM_SMEM);

    // ---- fc1: h = relu(x @ fc1_w^T + fc1_b)   (K=1024, kshift=10)
    cvt_a_k<<<(4096u * 1024u) / 256, 256>>>(x, a2, 10, (size_t)4096 * 1024);
    cvt_w_k<<<(512u * 1024u) / 256, 256>>>(fc1_w, w2, 512, 10, (size_t)512 * 1024);
    gemm_mma<<<dim3(4, 32), 256, GM_SMEM>>>(a2, w2, fc1_b, h, 512, 3072, 1, 0);

    for (int layer = 0; layer < 2; layer++) {
        layernorm_k<<<L, 256>>>(h, ln_w + layer * DM, ln_b + layer * DM, hn);
        // in_proj: zx = hn @ Wip^T   (K=512, N=4640 -> Npad=4736)
        cvt_a_k<<<(4096u * 512u) / 256, 256>>>(hn, a2, 9, (size_t)4096 * 512);
        cvt_w_k<<<(4736u * 512u) / 256, 256>>>(in_proj + (size_t)layer * DPROJ * DM,
                                               w2, DPROJ, 9, (size_t)4736 * 512);
        gemm_mma<<<dim3(37, 32), 256, GM_SMEM>>>(a2, w2, nullptr, zx, DPROJ, 1536, 0, 0);

        conv_silu<<<dim3(CONVD / 256, L), 256>>>(conv_w + layer * CONVD * 4,
                                                 conv_b + layer * CONVD);
        dt_kernel<<<(L * NH) / 256, 256>>>(dt_bias + layer * NH);
        scan_kernel<<<NH * SPLIT, 256>>>(A_log + layer * NH, Dvec + layer * NH);
        gate_rms<<<L, 256>>>(rms_w + layer * DIN);

        // out_proj: h += yn @ Wout^T  (K=2048, N=512)
        cvt_a_k<<<(4096u * 2048u) / 256, 256>>>(yn, a2, 11, (size_t)4096 * 2048);
        cvt_w_k<<<(512u * 2048u) / 256, 256>>>(out_proj + (size_t)layer * DM * DIN,
                                               w2, DM, 11, (size_t)512 * 2048);
        gemm_mma<<<dim3(4, 32), 256, GM_SMEM>>>(a2, w2, nullptr, h, 512, 6144, 0, 1);
    }

    layernorm_k<<<L, 256>>>(h, norm_w, norm_b, hn);
    // att: s1 = tanh(hn @ att_w1^T + att_b1)  (K=512, N=128)
    cvt_a_k<<<(4096u * 512u) / 256, 256>>>(hn, a2, 9, (size_t)4096 * 512);
    cvt_w_k<<<(128u * 512u) / 256, 256>>>(att_w1, w2, 128, 9, (size_t)128 * 512);
    gemm_mma<<<dim3(1, 32), 256, GM_SMEM>>>(a2, w2, att_b1, s1, 128, 1536, 2, 0);

    alog_kernel<<<L / 8, 256>>>(att_w2, att_b2);
    softmax_l<<<1, 1024>>>();
    pooled_part<<<32, 512>>>();
    finalize_kernel<<<1, 512>>>(cls_w, cls_b, out, out_size);
}